// round 13
// baseline (speedup 1.0000x reference)
#include <cuda_runtime.h>
#include <cuda_fp16.h>
#include <cstdint>

// ---------------------------------------------------------------------------
// FusionLayer collapsed to: out = relu(X @ Wcat^T + bias')
// All GEMMs on the fp16 m16n8k16 NT core (fp32 accum), operands b32-permuted.
// R13: main GEMM + kmer pack split into row-halves on two streams so the
// second half of activation packing overlaps the first half of the main GEMM.
// Core = R9/R12 known-best (128x128, 2 CTA/SM, 3-stage, XOR-64B swizzle).
// ---------------------------------------------------------------------------

#define DIM_B    16384
#define DIM_KMER 4096
#define DIM_COV  1024
#define DIM_D    2048
#define DIM_KTOT 5120
#define BN_EPS   1e-5f
#define HALF_B   (DIM_B / 2)

// scratch (allocation-free rule: __device__ globals)
__device__ __half g_Xh[(size_t)DIM_B * DIM_KTOT];
__device__ __half g_Wh[DIM_D * DIM_KTOT];
__device__ __half g_Wvh[DIM_D * DIM_D];
__device__ __half g_Woh[DIM_D * DIM_D];
__device__ __half g_Wfh[DIM_D * 2 * DIM_D];
__device__ __half g_WcTh[DIM_COV * DIM_D];
__device__ __half g_WkTh[DIM_KMER * DIM_D];
__device__ __half g_M1th[DIM_COV * DIM_D];
__device__ __half g_M2th[DIM_COV * DIM_D];
__device__ float  g_bias[DIM_D];
__device__ float  g_t1[DIM_D];
__device__ float  g_t2[DIM_D];

// ------------------------------- helpers -----------------------------------

__device__ __forceinline__ uint32_t smem_cast(const void* p) {
    uint32_t r;
    asm volatile("{ .reg .u64 t; cvta.to.shared.u64 t, %1; cvt.u32.u64 %0, t; }"
                 : "=r"(r) : "l"(p));
    return r;
}

__device__ __forceinline__ void cp_async16(void* sdst, const void* gsrc) {
    uint32_t d = smem_cast(sdst);
    asm volatile("cp.async.cg.shared.global [%0], [%1], 16;\n" :: "r"(d), "l"(gsrc));
}

__device__ __forceinline__ void mma_fp16(float c[4], uint32_t a0, uint32_t a1,
                                         uint32_t a2, uint32_t a3,
                                         uint32_t b0, uint32_t b1) {
    asm volatile(
        "mma.sync.aligned.m16n8k16.row.col.f32.f16.f16.f32 "
        "{%0,%1,%2,%3}, {%4,%5,%6,%7}, {%8,%9}, {%0,%1,%2,%3};\n"
        : "+f"(c[0]), "+f"(c[1]), "+f"(c[2]), "+f"(c[3])
        : "r"(a0), "r"(a1), "r"(a2), "r"(a3), "r"(b0), "r"(b1));
}

__device__ __forceinline__ uint32_t pack_h2(float lo, float hi) {
    __half2 h = __floats2half2_rn(lo, hi);
    return *reinterpret_cast<uint32_t*>(&h);
}

// ===================== unified fp16 NT GEMM core ============================
// C-tile 128x128, 4 warps of 64x64, BK=64, 3-stage cp.async, XOR-64B swizzle,
// 2 CTAs/SM. EPI 0: fp32 bias+relu store; offs = row offset (main row-half).
// EPI 1: fp16 b32-permuted store (+opt BN scale); offs = column offset.
// Inner loop = R6/R9 known-best form.

#define HSTG 3
#define HSTAGE_BYTES 32768
#define HSMEM_TOTAL (HSTG * HSTAGE_BYTES)

template<int EPI>
__global__ void __launch_bounds__(128, 2)
gemm_h_kernel(const __half* __restrict__ A, int lda,
              const __half* __restrict__ Bt, int ldb,
              void* __restrict__ Cv, int ldc, int offs, int K,
              const float* __restrict__ aux1, const float* __restrict__ aux2)
{
    extern __shared__ char smem[];
    const int tid  = threadIdx.x;
    const int lane = tid & 31;
    const int wid  = tid >> 5;
    const int wm   = wid >> 1;
    const int wn   = wid & 1;
    const int g    = lane >> 2;
    const int tg   = lane & 3;
    const int bn   = blockIdx.x, bm = blockIdx.y;

    const int rowoff = (EPI == 0) ? offs : 0;   // row offset for main halves
    const int coloff = (EPI == 1) ? offs : 0;   // column offset for prep

    const __half* gA = A  + (size_t)(rowoff + bm * 128) * lda;
    const __half* gB = Bt + (size_t)(bn * 128) * ldb;

    float acc[4][8][4];
#pragma unroll
    for (int i = 0; i < 4; i++)
#pragma unroll
        for (int j = 0; j < 8; j++)
#pragma unroll
            for (int q = 0; q < 4; q++) acc[i][j][q] = 0.f;

    auto load_tile = [&](int slot, int kt) {
        char* stg = smem + slot * HSTAGE_BYTES;
        const int k0 = kt * 64;
#pragma unroll
        for (int i = 0; i < 8; i++) {
            int fid = tid + i * 128;
            int row = fid >> 3, c = fid & 7;
            cp_async16(stg + row * 128 + ((c * 16) ^ ((row & 1) << 6)),
                       gA + (size_t)row * lda + k0 + c * 8);
        }
#pragma unroll
        for (int i = 0; i < 8; i++) {
            int fid = tid + i * 128;
            int row = fid >> 3, c = fid & 7;
            cp_async16(stg + 16384 + row * 128 + ((c * 16) ^ ((row & 1) << 6)),
                       gB + (size_t)row * ldb + k0 + c * 8);
        }
        asm volatile("cp.async.commit_group;\n");
    };

    const int NKT = K / 64;
    load_tile(0, 0);
    load_tile(1, 1);

    for (int kt = 0; kt < NKT; kt++) {
        asm volatile("cp.async.wait_group %0;\n" :: "n"(1));
        __syncthreads();
        if (kt + 2 < NKT) load_tile((kt + 2) % HSTG, kt + 2);
        else asm volatile("cp.async.commit_group;\n");

        const char* pa = smem + (kt % HSTG) * HSTAGE_BYTES;
        const char* pb = pa + 16384;

#pragma unroll
        for (int b = 0; b < 2; b++) {            // two 64B (k32) blocks
            uint4 Af[8], Bf[8];
#pragma unroll
            for (int mt = 0; mt < 4; mt++) {
                int r0 = wm * 64 + mt * 16 + g;
                int r1 = r0 + 8;
                Af[2 * mt] = *reinterpret_cast<const uint4*>(
                    pa + r0 * 128 + ((b * 64 + tg * 16) ^ ((r0 & 1) << 6)));
                Af[2 * mt + 1] = *reinterpret_cast<const uint4*>(
                    pa + r1 * 128 + ((b * 64 + tg * 16) ^ ((r1 & 1) << 6)));
            }
#pragma unroll
            for (int nt = 0; nt < 8; nt++) {
                int r = wn * 64 + nt * 8 + g;
                Bf[nt] = *reinterpret_cast<const uint4*>(
                    pb + r * 128 + ((b * 64 + tg * 16) ^ ((r & 1) << 6)));
            }
            // permuted layout: .x/.y = k16-group0 (lo/hi), .z/.w = group1
#pragma unroll
            for (int grp = 0; grp < 2; grp++) {
#pragma unroll
                for (int mt = 0; mt < 4; mt++) {
                    uint32_t a0, a1, a2, a3;
                    if (grp == 0) {
                        a0 = Af[2 * mt].x; a1 = Af[2 * mt + 1].x;
                        a2 = Af[2 * mt].y; a3 = Af[2 * mt + 1].y;
                    } else {
                        a0 = Af[2 * mt].z; a1 = Af[2 * mt + 1].z;
                        a2 = Af[2 * mt].w; a3 = Af[2 * mt + 1].w;
                    }
#pragma unroll
                    for (int nt = 0; nt < 8; nt++) {
                        uint32_t b0, b1;
                        if (grp == 0) { b0 = Bf[nt].x; b1 = Bf[nt].y; }
                        else          { b0 = Bf[nt].z; b1 = Bf[nt].w; }
                        mma_fp16(acc[mt][nt], a0, a1, a2, a3, b0, b1);
                    }
                }
            }
        }
    }

    // ------------------------------ epilogue --------------------------------
#pragma unroll
    for (int mt = 0; mt < 4; mt++) {
        const int row = rowoff + bm * 128 + wm * 64 + mt * 16 + g;
        float s0 = 1.f, s1 = 1.f;
        if (EPI == 1 && aux1 != nullptr) {
            int prow = bm * 128 + wm * 64 + mt * 16 + g;
            s0 = aux1[prow]     * rsqrtf(aux2[prow]     + BN_EPS);
            s1 = aux1[prow + 8] * rsqrtf(aux2[prow + 8] + BN_EPS);
        }
#pragma unroll
        for (int nt = 0; nt < 8; nt++) {
            const int col = bn * 128 + wn * 64 + nt * 8 + tg * 2;
            if (EPI == 0) {
                float* C = reinterpret_cast<float*>(Cv);
                float b0 = __ldg(aux1 + col), b1 = __ldg(aux1 + col + 1);
                float2 v;
                v.x = fmaxf(acc[mt][nt][0] + b0, 0.f);
                v.y = fmaxf(acc[mt][nt][1] + b1, 0.f);
                *reinterpret_cast<float2*>(&C[(size_t)row * ldc + col]) = v;
                v.x = fmaxf(acc[mt][nt][2] + b0, 0.f);
                v.y = fmaxf(acc[mt][nt][3] + b1, 0.f);
                *reinterpret_cast<float2*>(&C[(size_t)(row + 8) * ldc + col]) = v;
            } else {
                uint32_t* Ch = reinterpret_cast<uint32_t*>(Cv);
                int prow = bm * 128 + wm * 64 + mt * 16 + g;
                int j = (coloff + col) >> 1;
                int dst = (j & ~15) + 4 * (j & 3) + ((j >> 2) & 3);
                Ch[(size_t)prow * ldc + dst]       = pack_h2(acc[mt][nt][0] * s0,
                                                             acc[mt][nt][1] * s0);
                Ch[(size_t)(prow + 8) * ldc + dst] = pack_h2(acc[mt][nt][2] * s1,
                                                             acc[mt][nt][3] * s1);
            }
        }
    }
}

// ===== pack row-major fp32 -> fp16, b32-permuted (strided source) ===========

__global__ void pack_fp16(const float* __restrict__ src, int lw, int src_stride,
                          size_t nrows, __half* __restrict__ dst,
                          int dst_stride, int dstoff)
{
    const int nblk = 1 << (lw - 5);
    const size_t total = nrows << (lw - 5);
    const size_t idx = (size_t)blockIdx.x * blockDim.x + threadIdx.x;
    if (idx >= total) return;
    const size_t b = idx >> (lw - 5);
    const int blk  = (int)(idx & (nblk - 1));
    const float4* s = reinterpret_cast<const float4*>(
        src + b * (size_t)src_stride + blk * 32);
    uint32_t h[16];
#pragma unroll
    for (int i = 0; i < 8; i++) {
        float4 v = s[i];
        h[2 * i]     = pack_h2(v.x, v.y);
        h[2 * i + 1] = pack_h2(v.z, v.w);
    }
    uint4* d = reinterpret_cast<uint4*>(dst + b * dst_stride + dstoff + blk * 32);
#pragma unroll
    for (int t = 0; t < 4; t++)
        d[t] = make_uint4(h[t], h[t + 4], h[t + 8], h[t + 12]);
}

// ====== fused transpose + fp16 permuted pack:  in fp32 [R,C] -> out [C,R] ===

__global__ void tpack_fp16(const float* __restrict__ in, int R, int C,
                           __half* __restrict__ out)
{
    __shared__ float t[32][33];
    const int bx = blockIdx.x * 32;
    const int by = blockIdx.y * 32;
    const int tx = threadIdx.x;
    const int ty = threadIdx.y;

#pragma unroll
    for (int j = 0; j < 2; j++) {
        int r = ty + j * 16;
        float2 v = *reinterpret_cast<const float2*>(
            in + (size_t)(by + r) * C + bx + 2 * tx);
        t[r][2 * tx]     = v.x;
        t[r][2 * tx + 1] = v.y;
    }
    __syncthreads();

    uint32_t* o32 = reinterpret_cast<uint32_t*>(out);
    const int dst = (by >> 1) + 4 * (tx & 3) + (tx >> 2);
#pragma unroll
    for (int j = 0; j < 2; j++) {
        int oy = ty + j * 16;
        uint32_t v = pack_h2(t[2 * tx][oy], t[2 * tx + 1][oy]);
        o32[(size_t)(bx + oy) * (R / 2) + dst] = v;
    }
}

// ==================== warp-per-row matvec (float4) ==========================

__global__ void matvec_fast(const float* __restrict__ A, int lda, int aoffs,
                            const float* __restrict__ x, int K,
                            const float* __restrict__ addv,
                            float* __restrict__ y, int accum)
{
    const int row  = blockIdx.x * 8 + (threadIdx.x >> 5);
    const int lane = threadIdx.x & 31;
    const float4* a4 = reinterpret_cast<const float4*>(A + (size_t)row * lda + aoffs);
    const float4* x4 = reinterpret_cast<const float4*>(x);
    float s = 0.f;
    for (int k = lane; k < K / 4; k += 32) {
        float4 a = a4[k], b = x4[k];
        s += a.x * b.x + a.y * b.y + a.z * b.z + a.w * b.w;
    }
#pragma unroll
    for (int o = 16; o > 0; o >>= 1) s += __shfl_xor_sync(0xffffffffu, s, o);
    if (lane == 0) {
        if (addv) s += addv[row];
        if (accum) s += y[row];
        y[row] = s;
    }
}

__global__ void bias_finalize_kernel(float* __restrict__ bias,
                                     const float* __restrict__ beta,
                                     const float* __restrict__ mean,
                                     const float* __restrict__ gamma,
                                     const float* __restrict__ rvar)
{
    int j = blockIdx.x * blockDim.x + threadIdx.x;
    if (j < DIM_D) {
        float s = gamma[j] * rsqrtf(rvar[j] + BN_EPS);
        bias[j] = beta[j] + s * (bias[j] - mean[j]);
    }
}

// ------------------------------- launcher ----------------------------------

extern "C" void kernel_launch(void* const* d_in, const int* in_sizes, int n_in,
                              void* d_out, int out_size)
{
    const float* kmer  = (const float*)d_in[0];
    const float* cov   = (const float*)d_in[1];
    const float* Wk    = (const float*)d_in[2];
    const float* bk    = (const float*)d_in[3];
    const float* Wc    = (const float*)d_in[4];
    const float* bc    = (const float*)d_in[5];
    const float* Wv    = (const float*)d_in[6];
    const float* bv    = (const float*)d_in[7];
    const float* Wo    = (const float*)d_in[8];
    const float* bo    = (const float*)d_in[9];
    const float* Wf    = (const float*)d_in[10];
    const float* bf    = (const float*)d_in[11];
    const float* gamma = (const float*)d_in[12];
    const float* beta  = (const float*)d_in[13];
    const float* mean  = (const float*)d_in[14];
    const float* var   = (const float*)d_in[15];
    float* out = (float*)d_out;

    __half *Xh, *Wh, *Wvh, *Woh, *Wfh, *WcTh, *WkTh, *M1th, *M2th;
    float *bias, *t1, *t2;
    cudaGetSymbolAddress((void**)&Xh,   g_Xh);
    cudaGetSymbolAddress((void**)&Wh,   g_Wh);
    cudaGetSymbolAddress((void**)&Wvh,  g_Wvh);
    cudaGetSymbolAddress((void**)&Woh,  g_Woh);
    cudaGetSymbolAddress((void**)&Wfh,  g_Wfh);
    cudaGetSymbolAddress((void**)&WcTh, g_WcTh);
    cudaGetSymbolAddress((void**)&WkTh, g_WkTh);
    cudaGetSymbolAddress((void**)&M1th, g_M1th);
    cudaGetSymbolAddress((void**)&M2th, g_M2th);
    cudaGetSymbolAddress((void**)&bias, g_bias);
    cudaGetSymbolAddress((void**)&t1,   g_t1);
    cudaGetSymbolAddress((void**)&t2,   g_t2);

    cudaFuncSetAttribute(gemm_h_kernel<0>, cudaFuncAttributeMaxDynamicSharedMemorySize, HSMEM_TOTAL);
    cudaFuncSetAttribute(gemm_h_kernel<1>, cudaFuncAttributeMaxDynamicSharedMemorySize, HSMEM_TOTAL);

    // lazy one-time stream/event setup (outside capture; deterministic work).
    static cudaStream_t s1 = nullptr, s2 = nullptr, s3 = nullptr;
    static cudaEvent_t evFork = nullptr, evWk = nullptr, evG3 = nullptr;
    static cudaEvent_t evP1 = nullptr, evJ2 = nullptr, evJ3 = nullptr;
    if (s1 == nullptr) {
        cudaStreamCreateWithFlags(&s1, cudaStreamNonBlocking);
        cudaStreamCreateWithFlags(&s2, cudaStreamNonBlocking);
        cudaStreamCreateWithFlags(&s3, cudaStreamNonBlocking);
        cudaEventCreateWithFlags(&evFork, cudaEventDisableTiming);
        cudaEventCreateWithFlags(&evWk,   cudaEventDisableTiming);
        cudaEventCreateWithFlags(&evG3,   cudaEventDisableTiming);
        cudaEventCreateWithFlags(&evP1,   cudaEventDisableTiming);
        cudaEventCreateWithFlags(&evJ2,   cudaEventDisableTiming);
        cudaEventCreateWithFlags(&evJ3,   cudaEventDisableTiming);
    }

    // ---- fork -------------------------------------------------------------
    cudaEventRecord(evFork, 0);
    cudaStreamWaitEvent(s1, evFork, 0);
    cudaStreamWaitEvent(s2, evFork, 0);
    cudaStreamWaitEvent(s3, evFork, 0);

    // ---- s1: Wk tpack (feeds G3), kmer pack halves --------------------------
    {
        dim3 blk(16, 16);
        dim3 gk(DIM_KMER / 32, DIM_D / 32);
        tpack_fp16<<<gk, blk, 0, s1>>>(Wk, DIM_D, DIM_KMER, WkTh);
    }
    cudaEventRecord(evWk, s1);
    pack_fp16<<<4096, 256, 0, s1>>>(kmer, 12, DIM_KMER, HALF_B, Xh, DIM_KTOT, 0);
    cudaEventRecord(evP1, s1);
    pack_fp16<<<4096, 256, 0, s1>>>(kmer + (size_t)HALF_B * DIM_KMER, 12, DIM_KMER,
                                    HALF_B, Xh + (size_t)HALF_B * DIM_KTOT,
                                    DIM_KTOT, 0);

    // ---- s0 (default): Wf LEFT pack -> G3 -----------------------------------
    pack_fp16<<<512, 256>>>(Wf, 11, 2 * DIM_D, DIM_D, Wfh, 2 * DIM_D, 0);
    cudaStreamWaitEvent(0, evWk, 0);
    {   // G3: Wh[:, 0:4096] = s * (Wf_l @ Wk)
        dim3 grid(DIM_KMER / 128, DIM_D / 128);   // (32, 16)
        gemm_h_kernel<1><<<grid, 128, HSMEM_TOTAL>>>(
            Wfh, 2 * DIM_D, WkTh, DIM_D, Wh, DIM_KTOT / 2, 0, DIM_D, gamma, var);
    }
    cudaEventRecord(evG3, 0);

    // ---- s3: cov pack + bias chain ------------------------------------------
    pack_fp16<<<2048, 256, 0, s3>>>(cov, 10, DIM_COV, DIM_B, Xh, DIM_KTOT, DIM_KMER);
    matvec_fast<<<DIM_D / 8, 256, 0, s3>>>(Wv, DIM_D, 0,         bc, DIM_D, bv,      t1,   0);
    matvec_fast<<<DIM_D / 8, 256, 0, s3>>>(Wo, DIM_D, 0,         t1, DIM_D, bo,      t2,   0);
    matvec_fast<<<DIM_D / 8, 256, 0, s3>>>(Wf, 2 * DIM_D, DIM_D, t2, DIM_D, bf,      bias, 0);
    matvec_fast<<<DIM_D / 8, 256, 0, s3>>>(Wf, 2 * DIM_D, 0,     bk, DIM_D, nullptr, bias, 1);
    bias_finalize_kernel<<<(DIM_D + 255) / 256, 256, 0, s3>>>(bias, beta, mean, gamma, var);
    cudaEventRecord(evJ3, s3);

    // ---- s2: Wf RIGHT pack + small weight chain (self-contained) ------------
    pack_fp16<<<512, 256, 0, s2>>>(Wf + DIM_D, 11, 2 * DIM_D, DIM_D,
                                   Wfh, 2 * DIM_D, DIM_D);
    {
        dim3 blk(16, 16);
        dim3 gc(DIM_COV / 32, DIM_D / 32);
        tpack_fp16<<<gc, blk, 0, s2>>>(Wc, DIM_D, DIM_COV, WcTh);
    }
    pack_fp16<<<512, 256, 0, s2>>>(Wv, 11, DIM_D, DIM_D, Wvh, DIM_D, 0);
    pack_fp16<<<512, 256, 0, s2>>>(Wo, 11, DIM_D, DIM_D, Woh, DIM_D, 0);
    {   // G1: M1th = (Wv @ Wc)^T
        dim3 grid(DIM_D / 128, DIM_COV / 128);
        gemm_h_kernel<1><<<grid, 128, HSMEM_TOTAL, s2>>>(
            WcTh, DIM_D, Wvh, DIM_D, M1th, DIM_D / 2, 0, DIM_D, nullptr, nullptr);
    }
    {   // G2: M2th = (Wo @ M1)^T
        dim3 grid(DIM_D / 128, DIM_COV / 128);
        gemm_h_kernel<1><<<grid, 128, HSMEM_TOTAL, s2>>>(
            M1th, DIM_D, Woh, DIM_D, M2th, DIM_D / 2, 0, DIM_D, nullptr, nullptr);
    }
    {   // G4: Wh[:, 4096:] = s * (Wf_r @ M2)
        dim3 grid(DIM_COV / 128, DIM_D / 128);
        gemm_h_kernel<1><<<grid, 128, HSMEM_TOTAL, s2>>>(
            Wfh + DIM_D, 2 * DIM_D, M2th, DIM_D, Wh, DIM_KTOT / 2, DIM_KMER, DIM_D, gamma, var);
    }
    cudaEventRecord(evJ2, s2);

    // ---- main GEMM half 1 (rows 0..8191) on s0 -------------------------------
    cudaStreamWaitEvent(0, evP1, 0);
    cudaStreamWaitEvent(0, evJ2, 0);
    cudaStreamWaitEvent(0, evJ3, 0);
    {
        dim3 grid(DIM_D / 128, HALF_B / 128);   // (16, 64)
        gemm_h_kernel<0><<<grid, 128, HSMEM_TOTAL>>>(
            Xh, DIM_KTOT, Wh, DIM_KTOT, out, DIM_D, 0, DIM_KTOT, bias, nullptr);
    }

    // ---- main GEMM half 2 (rows 8192..16383) on s1 (after pack_h2) ----------
    cudaStreamWaitEvent(s1, evG3, 0);
    cudaStreamWaitEvent(s1, evJ2, 0);
    cudaStreamWaitEvent(s1, evJ3, 0);
    {
        dim3 grid(DIM_D / 128, HALF_B / 128);   // (16, 64)
        gemm_h_kernel<0><<<grid, 128, HSMEM_TOTAL, s1>>>(
            Xh, DIM_KTOT, Wh, DIM_KTOT, out, DIM_D, HALF_B, DIM_KTOT, bias, nullptr);
    }

    // ---- join: default stream must see s1's main half complete ---------------
    cudaEventRecord(evP1, s1);            // reuse event as completion marker
    cudaStreamWaitEvent(0, evP1, 0);
}

// round 14
// speedup vs baseline: 1.0250x; 1.0250x over previous
#include <cuda_runtime.h>
#include <cuda_fp16.h>
#include <cstdint>

// ---------------------------------------------------------------------------
// FusionLayer collapsed to: out = relu(X @ Wcat^T + bias')
// All GEMMs on the fp16 m16n8k16 NT core (fp32 accum), operands b32-permuted.
// R14: R12 structure (best: 1228us) with Wf-left pack moved off the critical
// stream (s0 = wait + G3 only). No kernel-code changes vs R12.
// ---------------------------------------------------------------------------

#define DIM_B    16384
#define DIM_KMER 4096
#define DIM_COV  1024
#define DIM_D    2048
#define DIM_KTOT 5120
#define BN_EPS   1e-5f

// scratch (allocation-free rule: __device__ globals)
__device__ __half g_Xh[(size_t)DIM_B * DIM_KTOT];
__device__ __half g_Wh[DIM_D * DIM_KTOT];
__device__ __half g_Wvh[DIM_D * DIM_D];
__device__ __half g_Woh[DIM_D * DIM_D];
__device__ __half g_Wfh[DIM_D * 2 * DIM_D];
__device__ __half g_WcTh[DIM_COV * DIM_D];
__device__ __half g_WkTh[DIM_KMER * DIM_D];
__device__ __half g_M1th[DIM_COV * DIM_D];
__device__ __half g_M2th[DIM_COV * DIM_D];
__device__ float  g_bias[DIM_D];
__device__ float  g_t1[DIM_D];
__device__ float  g_t2[DIM_D];

// ------------------------------- helpers -----------------------------------

__device__ __forceinline__ uint32_t smem_cast(const void* p) {
    uint32_t r;
    asm volatile("{ .reg .u64 t; cvta.to.shared.u64 t, %1; cvt.u32.u64 %0, t; }"
                 : "=r"(r) : "l"(p));
    return r;
}

__device__ __forceinline__ void cp_async16(void* sdst, const void* gsrc) {
    uint32_t d = smem_cast(sdst);
    asm volatile("cp.async.cg.shared.global [%0], [%1], 16;\n" :: "r"(d), "l"(gsrc));
}

__device__ __forceinline__ void mma_fp16(float c[4], uint32_t a0, uint32_t a1,
                                         uint32_t a2, uint32_t a3,
                                         uint32_t b0, uint32_t b1) {
    asm volatile(
        "mma.sync.aligned.m16n8k16.row.col.f32.f16.f16.f32 "
        "{%0,%1,%2,%3}, {%4,%5,%6,%7}, {%8,%9}, {%0,%1,%2,%3};\n"
        : "+f"(c[0]), "+f"(c[1]), "+f"(c[2]), "+f"(c[3])
        : "r"(a0), "r"(a1), "r"(a2), "r"(a3), "r"(b0), "r"(b1));
}

__device__ __forceinline__ uint32_t pack_h2(float lo, float hi) {
    __half2 h = __floats2half2_rn(lo, hi);
    return *reinterpret_cast<uint32_t*>(&h);
}

// ===================== unified fp16 NT GEMM core ============================
// C-tile 128x128, 4 warps of 64x64, BK=64, 3-stage cp.async, XOR-64B swizzle,
// 2 CTAs/SM. EPI 0: fp32 bias+relu store. EPI 1: fp16 b32-permuted store
// (+optional BN row scale). Inner loop = R6/R9 known-best form.

#define HSTG 3
#define HSTAGE_BYTES 32768
#define HSMEM_TOTAL (HSTG * HSTAGE_BYTES)

template<int EPI>
__global__ void __launch_bounds__(128, 2)
gemm_h_kernel(const __half* __restrict__ A, int lda,
              const __half* __restrict__ Bt, int ldb,
              void* __restrict__ Cv, int ldc, int coffs, int K,
              const float* __restrict__ aux1, const float* __restrict__ aux2)
{
    extern __shared__ char smem[];
    const int tid  = threadIdx.x;
    const int lane = tid & 31;
    const int wid  = tid >> 5;
    const int wm   = wid >> 1;
    const int wn   = wid & 1;
    const int g    = lane >> 2;
    const int tg   = lane & 3;
    const int bn   = blockIdx.x, bm = blockIdx.y;

    const __half* gA = A  + (size_t)(bm * 128) * lda;
    const __half* gB = Bt + (size_t)(bn * 128) * ldb;

    float acc[4][8][4];
#pragma unroll
    for (int i = 0; i < 4; i++)
#pragma unroll
        for (int j = 0; j < 8; j++)
#pragma unroll
            for (int q = 0; q < 4; q++) acc[i][j][q] = 0.f;

    auto load_tile = [&](int slot, int kt) {
        char* stg = smem + slot * HSTAGE_BYTES;
        const int k0 = kt * 64;
#pragma unroll
        for (int i = 0; i < 8; i++) {
            int fid = tid + i * 128;
            int row = fid >> 3, c = fid & 7;
            cp_async16(stg + row * 128 + ((c * 16) ^ ((row & 1) << 6)),
                       gA + (size_t)row * lda + k0 + c * 8);
        }
#pragma unroll
        for (int i = 0; i < 8; i++) {
            int fid = tid + i * 128;
            int row = fid >> 3, c = fid & 7;
            cp_async16(stg + 16384 + row * 128 + ((c * 16) ^ ((row & 1) << 6)),
                       gB + (size_t)row * ldb + k0 + c * 8);
        }
        asm volatile("cp.async.commit_group;\n");
    };

    const int NKT = K / 64;
    load_tile(0, 0);
    load_tile(1, 1);

    for (int kt = 0; kt < NKT; kt++) {
        asm volatile("cp.async.wait_group %0;\n" :: "n"(1));
        __syncthreads();
        if (kt + 2 < NKT) load_tile((kt + 2) % HSTG, kt + 2);
        else asm volatile("cp.async.commit_group;\n");

        const char* pa = smem + (kt % HSTG) * HSTAGE_BYTES;
        const char* pb = pa + 16384;

#pragma unroll
        for (int b = 0; b < 2; b++) {            // two 64B (k32) blocks
            uint4 Af[8], Bf[8];
#pragma unroll
            for (int mt = 0; mt < 4; mt++) {
                int r0 = wm * 64 + mt * 16 + g;
                int r1 = r0 + 8;
                Af[2 * mt] = *reinterpret_cast<const uint4*>(
                    pa + r0 * 128 + ((b * 64 + tg * 16) ^ ((r0 & 1) << 6)));
                Af[2 * mt + 1] = *reinterpret_cast<const uint4*>(
                    pa + r1 * 128 + ((b * 64 + tg * 16) ^ ((r1 & 1) << 6)));
            }
#pragma unroll
            for (int nt = 0; nt < 8; nt++) {
                int r = wn * 64 + nt * 8 + g;
                Bf[nt] = *reinterpret_cast<const uint4*>(
                    pb + r * 128 + ((b * 64 + tg * 16) ^ ((r & 1) << 6)));
            }
            // permuted layout: .x/.y = k16-group0 (lo/hi), .z/.w = group1
#pragma unroll
            for (int grp = 0; grp < 2; grp++) {
#pragma unroll
                for (int mt = 0; mt < 4; mt++) {
                    uint32_t a0, a1, a2, a3;
                    if (grp == 0) {
                        a0 = Af[2 * mt].x; a1 = Af[2 * mt + 1].x;
                        a2 = Af[2 * mt].y; a3 = Af[2 * mt + 1].y;
                    } else {
                        a0 = Af[2 * mt].z; a1 = Af[2 * mt + 1].z;
                        a2 = Af[2 * mt].w; a3 = Af[2 * mt + 1].w;
                    }
#pragma unroll
                    for (int nt = 0; nt < 8; nt++) {
                        uint32_t b0, b1;
                        if (grp == 0) { b0 = Bf[nt].x; b1 = Bf[nt].y; }
                        else          { b0 = Bf[nt].z; b1 = Bf[nt].w; }
                        mma_fp16(acc[mt][nt], a0, a1, a2, a3, b0, b1);
                    }
                }
            }
        }
    }

    // ------------------------------ epilogue --------------------------------
#pragma unroll
    for (int mt = 0; mt < 4; mt++) {
        const int row = bm * 128 + wm * 64 + mt * 16 + g;
        float s0 = 1.f, s1 = 1.f;
        if (EPI == 1 && aux1 != nullptr) {
            s0 = aux1[row]     * rsqrtf(aux2[row]     + BN_EPS);
            s1 = aux1[row + 8] * rsqrtf(aux2[row + 8] + BN_EPS);
        }
#pragma unroll
        for (int nt = 0; nt < 8; nt++) {
            const int col = bn * 128 + wn * 64 + nt * 8 + tg * 2;
            if (EPI == 0) {
                float* C = reinterpret_cast<float*>(Cv);
                float b0 = aux1[col], b1 = aux1[col + 1];
                float2 v;
                v.x = fmaxf(acc[mt][nt][0] + b0, 0.f);
                v.y = fmaxf(acc[mt][nt][1] + b1, 0.f);
                *reinterpret_cast<float2*>(&C[(size_t)row * ldc + col]) = v;
                v.x = fmaxf(acc[mt][nt][2] + b0, 0.f);
                v.y = fmaxf(acc[mt][nt][3] + b1, 0.f);
                *reinterpret_cast<float2*>(&C[(size_t)(row + 8) * ldc + col]) = v;
            } else {
                uint32_t* Ch = reinterpret_cast<uint32_t*>(Cv);
                int j = (coffs + col) >> 1;
                int dst = (j & ~15) + 4 * (j & 3) + ((j >> 2) & 3);
                Ch[(size_t)row * ldc + dst]       = pack_h2(acc[mt][nt][0] * s0,
                                                            acc[mt][nt][1] * s0);
                Ch[(size_t)(row + 8) * ldc + dst] = pack_h2(acc[mt][nt][2] * s1,
                                                            acc[mt][nt][3] * s1);
            }
        }
    }
}

// ===== pack row-major fp32 -> fp16, b32-permuted (strided source) ===========

__global__ void pack_fp16(const float* __restrict__ src, int lw, int src_stride,
                          size_t nrows, __half* __restrict__ dst,
                          int dst_stride, int dstoff)
{
    const int nblk = 1 << (lw - 5);
    const size_t total = nrows << (lw - 5);
    const size_t idx = (size_t)blockIdx.x * blockDim.x + threadIdx.x;
    if (idx >= total) return;
    const size_t b = idx >> (lw - 5);
    const int blk  = (int)(idx & (nblk - 1));
    const float4* s = reinterpret_cast<const float4*>(
        src + b * (size_t)src_stride + blk * 32);
    uint32_t h[16];
#pragma unroll
    for (int i = 0; i < 8; i++) {
        float4 v = s[i];
        h[2 * i]     = pack_h2(v.x, v.y);
        h[2 * i + 1] = pack_h2(v.z, v.w);
    }
    uint4* d = reinterpret_cast<uint4*>(dst + b * dst_stride + dstoff + blk * 32);
#pragma unroll
    for (int t = 0; t < 4; t++)
        d[t] = make_uint4(h[t], h[t + 4], h[t + 8], h[t + 12]);
}

// ====== fused transpose + fp16 permuted pack:  in fp32 [R,C] -> out [C,R] ===

__global__ void tpack_fp16(const float* __restrict__ in, int R, int C,
                           __half* __restrict__ out)
{
    __shared__ float t[32][33];
    const int bx = blockIdx.x * 32;
    const int by = blockIdx.y * 32;
    const int tx = threadIdx.x;
    const int ty = threadIdx.y;

#pragma unroll
    for (int j = 0; j < 2; j++) {
        int r = ty + j * 16;
        float2 v = *reinterpret_cast<const float2*>(
            in + (size_t)(by + r) * C + bx + 2 * tx);
        t[r][2 * tx]     = v.x;
        t[r][2 * tx + 1] = v.y;
    }
    __syncthreads();

    uint32_t* o32 = reinterpret_cast<uint32_t*>(out);
    const int dst = (by >> 1) + 4 * (tx & 3) + (tx >> 2);
#pragma unroll
    for (int j = 0; j < 2; j++) {
        int oy = ty + j * 16;
        uint32_t v = pack_h2(t[2 * tx][oy], t[2 * tx + 1][oy]);
        o32[(size_t)(bx + oy) * (R / 2) + dst] = v;
    }
}

// ==================== warp-per-row matvec (float4) ==========================

__global__ void matvec_fast(const float* __restrict__ A, int lda, int aoffs,
                            const float* __restrict__ x, int K,
                            const float* __restrict__ addv,
                            float* __restrict__ y, int accum)
{
    const int row  = blockIdx.x * 8 + (threadIdx.x >> 5);
    const int lane = threadIdx.x & 31;
    const float4* a4 = reinterpret_cast<const float4*>(A + (size_t)row * lda + aoffs);
    const float4* x4 = reinterpret_cast<const float4*>(x);
    float s = 0.f;
    for (int k = lane; k < K / 4; k += 32) {
        float4 a = a4[k], b = x4[k];
        s += a.x * b.x + a.y * b.y + a.z * b.z + a.w * b.w;
    }
#pragma unroll
    for (int o = 16; o > 0; o >>= 1) s += __shfl_xor_sync(0xffffffffu, s, o);
    if (lane == 0) {
        if (addv) s += addv[row];
        if (accum) s += y[row];
        y[row] = s;
    }
}

__global__ void bias_finalize_kernel(float* __restrict__ bias,
                                     const float* __restrict__ beta,
                                     const float* __restrict__ mean,
                                     const float* __restrict__ gamma,
                                     const float* __restrict__ rvar)
{
    int j = blockIdx.x * blockDim.x + threadIdx.x;
    if (j < DIM_D) {
        float s = gamma[j] * rsqrtf(rvar[j] + BN_EPS);
        bias[j] = beta[j] + s * (bias[j] - mean[j]);
    }
}

// ------------------------------- launcher ----------------------------------

extern "C" void kernel_launch(void* const* d_in, const int* in_sizes, int n_in,
                              void* d_out, int out_size)
{
    const float* kmer  = (const float*)d_in[0];
    const float* cov   = (const float*)d_in[1];
    const float* Wk    = (const float*)d_in[2];
    const float* bk    = (const float*)d_in[3];
    const float* Wc    = (const float*)d_in[4];
    const float* bc    = (const float*)d_in[5];
    const float* Wv    = (const float*)d_in[6];
    const float* bv    = (const float*)d_in[7];
    const float* Wo    = (const float*)d_in[8];
    const float* bo    = (const float*)d_in[9];
    const float* Wf    = (const float*)d_in[10];
    const float* bf    = (const float*)d_in[11];
    const float* gamma = (const float*)d_in[12];
    const float* beta  = (const float*)d_in[13];
    const float* mean  = (const float*)d_in[14];
    const float* var   = (const float*)d_in[15];
    float* out = (float*)d_out;

    __half *Xh, *Wh, *Wvh, *Woh, *Wfh, *WcTh, *WkTh, *M1th, *M2th;
    float *bias, *t1, *t2;
    cudaGetSymbolAddress((void**)&Xh,   g_Xh);
    cudaGetSymbolAddress((void**)&Wh,   g_Wh);
    cudaGetSymbolAddress((void**)&Wvh,  g_Wvh);
    cudaGetSymbolAddress((void**)&Woh,  g_Woh);
    cudaGetSymbolAddress((void**)&Wfh,  g_Wfh);
    cudaGetSymbolAddress((void**)&WcTh, g_WcTh);
    cudaGetSymbolAddress((void**)&WkTh, g_WkTh);
    cudaGetSymbolAddress((void**)&M1th, g_M1th);
    cudaGetSymbolAddress((void**)&M2th, g_M2th);
    cudaGetSymbolAddress((void**)&bias, g_bias);
    cudaGetSymbolAddress((void**)&t1,   g_t1);
    cudaGetSymbolAddress((void**)&t2,   g_t2);

    cudaFuncSetAttribute(gemm_h_kernel<0>, cudaFuncAttributeMaxDynamicSharedMemorySize, HSMEM_TOTAL);
    cudaFuncSetAttribute(gemm_h_kernel<1>, cudaFuncAttributeMaxDynamicSharedMemorySize, HSMEM_TOTAL);

    // lazy one-time stream/event setup (outside capture; deterministic work).
    static cudaStream_t s1 = nullptr, s2 = nullptr, s3 = nullptr;
    static cudaEvent_t evFork = nullptr, evWk = nullptr, evWfL = nullptr;
    static cudaEvent_t evJ1 = nullptr, evJ2 = nullptr, evJ3 = nullptr;
    if (s1 == nullptr) {
        cudaStreamCreateWithFlags(&s1, cudaStreamNonBlocking);
        cudaStreamCreateWithFlags(&s2, cudaStreamNonBlocking);
        cudaStreamCreateWithFlags(&s3, cudaStreamNonBlocking);
        cudaEventCreateWithFlags(&evFork, cudaEventDisableTiming);
        cudaEventCreateWithFlags(&evWk,   cudaEventDisableTiming);
        cudaEventCreateWithFlags(&evWfL,  cudaEventDisableTiming);
        cudaEventCreateWithFlags(&evJ1,   cudaEventDisableTiming);
        cudaEventCreateWithFlags(&evJ2,   cudaEventDisableTiming);
        cudaEventCreateWithFlags(&evJ3,   cudaEventDisableTiming);
    }

    // ---- fork -------------------------------------------------------------
    cudaEventRecord(evFork, 0);
    cudaStreamWaitEvent(s1, evFork, 0);
    cudaStreamWaitEvent(s2, evFork, 0);
    cudaStreamWaitEvent(s3, evFork, 0);

    // ---- s1: Wk tpack (feeds G3 on s0), then kmer pack ----------------------
    {
        dim3 blk(16, 16);
        dim3 gk(DIM_KMER / 32, DIM_D / 32);
        tpack_fp16<<<gk, blk, 0, s1>>>(Wk, DIM_D, DIM_KMER, WkTh);
    }
    cudaEventRecord(evWk, s1);
    pack_fp16<<<8192, 256, 0, s1>>>(kmer, 12, DIM_KMER, DIM_B, Xh, DIM_KTOT, 0);
    cudaEventRecord(evJ1, s1);

    // ---- s3: Wf LEFT pack (feeds G3), cov pack + bias chain ------------------
    pack_fp16<<<512, 256, 0, s3>>>(Wf, 11, 2 * DIM_D, DIM_D, Wfh, 2 * DIM_D, 0);
    cudaEventRecord(evWfL, s3);
    pack_fp16<<<2048, 256, 0, s3>>>(cov, 10, DIM_COV, DIM_B, Xh, DIM_KTOT, DIM_KMER);
    matvec_fast<<<DIM_D / 8, 256, 0, s3>>>(Wv, DIM_D, 0,         bc, DIM_D, bv,      t1,   0);
    matvec_fast<<<DIM_D / 8, 256, 0, s3>>>(Wo, DIM_D, 0,         t1, DIM_D, bo,      t2,   0);
    matvec_fast<<<DIM_D / 8, 256, 0, s3>>>(Wf, 2 * DIM_D, DIM_D, t2, DIM_D, bf,      bias, 0);
    matvec_fast<<<DIM_D / 8, 256, 0, s3>>>(Wf, 2 * DIM_D, 0,     bk, DIM_D, nullptr, bias, 1);
    bias_finalize_kernel<<<(DIM_D + 255) / 256, 256, 0, s3>>>(bias, beta, mean, gamma, var);
    cudaEventRecord(evJ3, s3);

    // ---- s0 (default): G3 only (critical path) ------------------------------
    cudaStreamWaitEvent(0, evWfL, 0);
    cudaStreamWaitEvent(0, evWk, 0);
    {   // G3: Wh[:, 0:4096] = s * (Wf_l @ Wk)
        dim3 grid(DIM_KMER / 128, DIM_D / 128);   // (32, 16)
        gemm_h_kernel<1><<<grid, 128, HSMEM_TOTAL>>>(
            Wfh, 2 * DIM_D, WkTh, DIM_D, Wh, DIM_KTOT / 2, 0, DIM_D, gamma, var);
    }

    // ---- s2: Wf RIGHT pack + small weight chain (self-contained) ------------
    pack_fp16<<<512, 256, 0, s2>>>(Wf + DIM_D, 11, 2 * DIM_D, DIM_D,
                                   Wfh, 2 * DIM_D, DIM_D);
    {
        dim3 blk(16, 16);
        dim3 gc(DIM_COV / 32, DIM_D / 32);
        tpack_fp16<<<gc, blk, 0, s2>>>(Wc, DIM_D, DIM_COV, WcTh);
    }
    pack_fp16<<<512, 256, 0, s2>>>(Wv, 11, DIM_D, DIM_D, Wvh, DIM_D, 0);
    pack_fp16<<<512, 256, 0, s2>>>(Wo, 11, DIM_D, DIM_D, Woh, DIM_D, 0);
    {   // G1: M1th = (Wv @ Wc)^T  via core(WcTh, Wvh)
        dim3 grid(DIM_D / 128, DIM_COV / 128);
        gemm_h_kernel<1><<<grid, 128, HSMEM_TOTAL, s2>>>(
            WcTh, DIM_D, Wvh, DIM_D, M1th, DIM_D / 2, 0, DIM_D, nullptr, nullptr);
    }
    {   // G2: M2th = (Wo @ M1)^T  via core(M1th, Woh)
        dim3 grid(DIM_D / 128, DIM_COV / 128);
        gemm_h_kernel<1><<<grid, 128, HSMEM_TOTAL, s2>>>(
            M1th, DIM_D, Woh, DIM_D, M2th, DIM_D / 2, 0, DIM_D, nullptr, nullptr);
    }
    {   // G4: Wh[:, 4096:] = s * (Wf_r @ M2)
        dim3 grid(DIM_COV / 128, DIM_D / 128);
        gemm_h_kernel<1><<<grid, 128, HSMEM_TOTAL, s2>>>(
            Wfh + DIM_D, 2 * DIM_D, M2th, DIM_D, Wh, DIM_KTOT / 2, DIM_KMER, DIM_D, gamma, var);
    }
    cudaEventRecord(evJ2, s2);

    // ---- join + main fused GEMM (known-best core) ----------------------------
    cudaStreamWaitEvent(0, evJ1, 0);
    cudaStreamWaitEvent(0, evJ2, 0);
    cudaStreamWaitEvent(0, evJ3, 0);
    {
        dim3 grid(DIM_D / 128, DIM_B / 128);   // (16, 128)
        gemm_h_kernel<0><<<grid, 128, HSMEM_TOTAL>>>(
            Xh, DIM_KTOT, Wh, DIM_KTOT, out, DIM_D, 0, DIM_KTOT, bias, nullptr);
    }
}